// round 14
// baseline (speedup 1.0000x reference)
// R11: resubmission of R8 kernel — round 8->11 runs failed on GB300 container
// infra ("container failed twice"), not on kernel compile/run. No code change.
// GEMM mainloop: 4-stage cp.async pipeline (BK=16), single __syncthreads per
// k-tile, staging overlapped with mma, fragment addresses folded.
#include <cuda_runtime.h>
#include <stdint.h>

#define BB  8
#define TT  1024
#define EE  1024
#define HH  16
#define HSZ 64
#define MTOT (BB*TT)
#define XN  ((size_t)MTOT*EE)
#define WN  ((size_t)EE*EE)

__device__ __align__(16) float g_q[(size_t)BB*HH*TT*HSZ];   // tf32, pre-scaled
__device__ __align__(16) float g_k[(size_t)BB*HH*TT*HSZ];   // tf32
__device__ __align__(16) float g_v[(size_t)BB*HH*TT*HSZ];   // tf32
__device__ __align__(16) float g_att[XN];
__device__ __align__(16) float g_xt[XN];
__device__ __align__(16) float g_wt[4*WN];

__device__ __forceinline__ unsigned f2tf32(float f) {
    unsigned r; asm("cvt.rna.tf32.f32 %0, %1;" : "=r"(r) : "f"(f));
    return r;
}
__device__ __forceinline__ void mma_tf32(float c[4],
    unsigned a0, unsigned a1, unsigned a2, unsigned a3,
    unsigned b0, unsigned b1)
{
    asm volatile(
        "mma.sync.aligned.m16n8k8.row.col.f32.tf32.tf32.f32 "
        "{%0,%1,%2,%3}, {%4,%5,%6,%7}, {%8,%9}, {%0,%1,%2,%3};"
        : "+f"(c[0]), "+f"(c[1]), "+f"(c[2]), "+f"(c[3])
        : "r"(a0), "r"(a1), "r"(a2), "r"(a3), "r"(b0), "r"(b1));
}
__device__ __forceinline__ uint32_t s2u(const void* p) {
    uint32_t a;
    asm("{ .reg .u64 t; cvta.to.shared.u64 t, %1; cvt.u32.u64 %0, t; }"
        : "=r"(a) : "l"(p));
    return a;
}
__device__ __forceinline__ void cpa16(uint32_t dst, const void* src) {
    asm volatile("cp.async.cg.shared.global [%0], [%1], 16;"
                 :: "r"(dst), "l"(src) : "memory");
}
#define CP_COMMIT() asm volatile("cp.async.commit_group;" ::: "memory")
#define CP_WAIT2()  asm volatile("cp.async.wait_group 2;" ::: "memory")
#define CP_WAIT0()  asm volatile("cp.async.wait_group 0;" ::: "memory")

// ---------------------------------------------------------------------------
// prepass: round x and the 4 weight matrices to tf32 precision
// ---------------------------------------------------------------------------
__global__ __launch_bounds__(256) void round_tf32_kernel(
    const float* __restrict__ x,  const float* __restrict__ wq,
    const float* __restrict__ wk, const float* __restrict__ wv,
    const float* __restrict__ wp)
{
    const size_t i4 = (size_t)blockIdx.x * blockDim.x + threadIdx.x;
    const size_t e  = i4 * 4;
    if (e >= XN + 4 * WN) return;

    const float* src; float* dst; size_t off;
    if (e < XN) { src = x; dst = g_xt; off = e; }
    else {
        const size_t we = e - XN;
        const int z = (int)(we / WN);
        off = we - (size_t)z * WN;
        src = (z == 0) ? wq : (z == 1) ? wk : (z == 2) ? wv : wp;
        dst = g_wt + (size_t)z * WN;
    }
    float4 v = *(const float4*)(src + off);
    v.x = __uint_as_float(f2tf32(v.x));
    v.y = __uint_as_float(f2tf32(v.y));
    v.z = __uint_as_float(f2tf32(v.z));
    v.w = __uint_as_float(f2tf32(v.w));
    *(float4*)(dst + off) = v;
}

// ---------------------------------------------------------------------------
// TF32 GEMM: C = A @ W^T. 128x128 tile, BK=16, 8 warps (4m x 2n).
// 4-stage cp.async pipeline, ONE __syncthreads per k-tile: staging for
// tile c+3 goes to buffer (c+3)&3 == (c-1)&3, proven drained by the
// top-of-loop barrier (all warps finished tile c-1's mma before arriving).
// ---------------------------------------------------------------------------
#define LDW   24
#define TILEF (128*LDW)              // 3072 floats per matrix tile
#define STAGEB (2*TILEF*4)           // 24576 B per stage (A+B)
#define GSMEM (4*STAGEB)             // 98304 B

__device__ __forceinline__ void gemm_stage(
    uint32_t sbuf, const float* __restrict__ A, const float* __restrict__ W,
    int c)
{
    const int tid = threadIdx.x;
    // 1024 16B-chunks: [matrix(2)][row(128)][chunk(4)]
    #pragma unroll
    for (int u = 0; u < 4; ++u) {
        const int i   = tid + u * 256;
        const int mat = i >> 9;
        const int j   = i & 511;
        const int row = j >> 2;
        const int cq  = (j & 3) * 4;
        const float* src = (mat ? W : A) + (size_t)row * EE + c * 16 + cq;
        const uint32_t dst = sbuf + (uint32_t)(mat * TILEF + row * LDW + cq) * 4;
        cpa16(dst, src);
    }
}

__device__ __forceinline__ void gemm_core(
    const float* __restrict__ A, const float* __restrict__ W,
    float acc[2][8][4], float* sm)
{
    const int tid  = threadIdx.x;
    const int wid  = tid >> 5;
    const int lane = tid & 31;
    const int grp  = lane >> 2;
    const int tig  = lane & 3;
    const int warpM = (wid & 3) * 32;
    const int warpN = (wid >> 2) * 64;
    const uint32_t sb = s2u(sm);

    gemm_stage(sb + 0 * STAGEB, A, W, 0); CP_COMMIT();
    gemm_stage(sb + 1 * STAGEB, A, W, 1); CP_COMMIT();
    gemm_stage(sb + 2 * STAGEB, A, W, 2); CP_COMMIT();

    const int NKT = EE / 16;   // 64
    const int aoff = (warpM + grp) * LDW + 2 * tig;
    const int boff = (warpN + grp) * LDW + 2 * tig;

    #pragma unroll 1
    for (int c = 0; c < NKT; ++c) {
        CP_WAIT2();
        __syncthreads();

        // stage tile c+3 into buffer (c+3)&3 == (c-1)&3 (free: barrier above
        // proves every warp finished tile c-1's mma). Overlaps this tile's mma.
        if (c + 3 < NKT)
            gemm_stage(sb + (uint32_t)((c + 3) & 3) * STAGEB, A, W, c + 3);
        CP_COMMIT();

        const float* as = sm + (c & 3) * (2 * TILEF);
        const float* aF = as + aoff;
        const float* bF = as + TILEF + boff;

        #pragma unroll
        for (int ks = 0; ks < 2; ++ks) {
            const int ko = ks * 8;
            float2 a02_0 = *(const float2*)(aF + ko);
            float2 a13_0 = *(const float2*)(aF + 8 * LDW + ko);
            float2 a02_1 = *(const float2*)(aF + 16 * LDW + ko);
            float2 a13_1 = *(const float2*)(aF + 24 * LDW + ko);
            #pragma unroll
            for (int j = 0; j < 8; ++j) {
                float2 b01 = *(const float2*)(bF + j * 8 * LDW + ko);
                mma_tf32(acc[0][j],
                    __float_as_uint(a02_0.x), __float_as_uint(a13_0.x),
                    __float_as_uint(a02_0.y), __float_as_uint(a13_0.y),
                    __float_as_uint(b01.x),   __float_as_uint(b01.y));
                mma_tf32(acc[1][j],
                    __float_as_uint(a02_1.x), __float_as_uint(a13_1.x),
                    __float_as_uint(a02_1.y), __float_as_uint(a13_1.y),
                    __float_as_uint(b01.x),   __float_as_uint(b01.y));
            }
        }
    }
}

// QKV: epilogue writes tf32-rounded q/k/v, q pre-scaled by HS^-0.5 = 0.125.
__global__ __launch_bounds__(256, 2) void qkv_gemm_kernel()
{
    extern __shared__ __align__(16) float sm[];
    const int z = blockIdx.z;
    const int blockM = blockIdx.y * 128, blockN = blockIdx.x * 128;

    float acc[2][8][4];
    #pragma unroll
    for (int i = 0; i < 2; ++i)
        #pragma unroll
        for (int j = 0; j < 8; ++j)
            #pragma unroll
            for (int c = 0; c < 4; ++c) acc[i][j][c] = 0.f;

    gemm_core(g_xt + (size_t)blockM * EE,
              g_wt + (size_t)z * WN + (size_t)blockN * EE, acc, sm);

    float* dst = (z == 0) ? g_q : (z == 1) ? g_k : g_v;
    const float scl = (z == 0) ? 0.125f : 1.0f;
    const int wid = threadIdx.x >> 5, lane = threadIdx.x & 31;
    const int grp = lane >> 2, tig = lane & 3;
    const int warpM = (wid & 3) * 32, warpN = (wid >> 2) * 64;

    #pragma unroll
    for (int i = 0; i < 2; ++i) {
        #pragma unroll
        for (int j = 0; j < 8; ++j) {
            const int col = blockN + warpN + j*8 + tig*2;
            const int h = col >> 6, d = col & 63;
            #pragma unroll
            for (int rh = 0; rh < 2; ++rh) {
                const int row = blockM + warpM + i*16 + grp + rh*8;
                const int b = row >> 10, t = row & (TT-1);
                float2 v2 = make_float2(
                    __uint_as_float(f2tf32(acc[i][j][rh*2]   * scl)),
                    __uint_as_float(f2tf32(acc[i][j][rh*2+1] * scl)));
                *(float2*)&dst[((size_t)(b*HH + h)*TT + t)*HSZ + d] = v2;
            }
        }
    }
}

__global__ __launch_bounds__(256, 2) void proj_gemm_kernel(float* __restrict__ out)
{
    extern __shared__ __align__(16) float sm[];
    const int blockM = blockIdx.y * 128, blockN = blockIdx.x * 128;

    float acc[2][8][4];
    #pragma unroll
    for (int i = 0; i < 2; ++i)
        #pragma unroll
        for (int j = 0; j < 8; ++j)
            #pragma unroll
            for (int c = 0; c < 4; ++c) acc[i][j][c] = 0.f;

    gemm_core(g_att + (size_t)blockM * EE,
              g_wt + 3 * WN + (size_t)blockN * EE, acc, sm);

    const int wid = threadIdx.x >> 5, lane = threadIdx.x & 31;
    const int grp = lane >> 2, tig = lane & 3;
    const int warpM = (wid & 3) * 32, warpN = (wid >> 2) * 64;

    #pragma unroll
    for (int i = 0; i < 2; ++i) {
        #pragma unroll
        for (int j = 0; j < 8; ++j) {
            const int col = blockN + warpN + j*8 + tig*2;
            #pragma unroll
            for (int rh = 0; rh < 2; ++rh) {
                const int row = blockM + warpM + i*16 + grp + rh*8;
                float2 v2 = make_float2(acc[i][j][rh*2], acc[i][j][rh*2+1]);
                *(float2*)&out[(size_t)row*EE + col] = v2;
            }
        }
    }
}

// ---------------------------------------------------------------------------
// Causal flash attention, mma.sync tf32 (unchanged from R6/R8).
// ---------------------------------------------------------------------------
#define ALDW 72
#define VLDW 68
#define ASMEM ((128*ALDW + 64*ALDW + 64*VLDW + 128*ALDW) * 4)

__global__ __launch_bounds__(256, 2) void attn_mma_kernel()
{
    extern __shared__ __align__(16) float sm[];
    float* Qs = sm;
    float* Ks = Qs + 128 * ALDW;
    float* Vs = Ks + 64 * ALDW;
    float* Ps = Vs + 64 * VLDW;

    const int qb = blockIdx.x, h = blockIdx.y, b = blockIdx.z;
    const float* qp = g_q + ((size_t)(b * HH + h) * TT + qb * 128) * HSZ;
    const float* kp = g_k + ((size_t)(b * HH + h) * TT) * HSZ;
    const float* vp = g_v + ((size_t)(b * HH + h) * TT) * HSZ;

    const int tid  = threadIdx.x;
    const int wid  = tid >> 5;
    const int lane = tid & 31;
    const int grp  = lane >> 2;
    const int tig  = lane & 3;
    const int wm   = wid * 16;
    const uint32_t sb = s2u(sm);
    const uint32_t sbK = sb + 128 * ALDW * 4;
    const uint32_t sbV = sbK + 64 * ALDW * 4;

    #pragma unroll
    for (int u = 0; u < 8; ++u) {
        const int i = tid + u * 256;
        const int row = i >> 4, cq = (i & 15) * 4;
        cpa16(sb + (uint32_t)(row * ALDW + cq) * 4,
              qp + (size_t)row * HSZ + cq);
    }

    float m[2], l[2], o[8][4];
    m[0] = m[1] = -1e30f; l[0] = l[1] = 0.f;
    #pragma unroll
    for (int j = 0; j < 8; ++j)
        #pragma unroll
        for (int c = 0; c < 4; ++c) o[j][c] = 0.f;

    const int ntiles = 2 * qb + 2;

    for (int kt = 0; kt < ntiles; ++kt) {
        #pragma unroll
        for (int u = 0; u < 4; ++u) {
            const int i = tid + u * 256;
            const int s = i >> 4, cq = (i & 15) * 4;
            const size_t go = (size_t)(kt * 64 + s) * HSZ + cq;
            cpa16(sbK + (uint32_t)(s * ALDW + cq) * 4, kp + go);
            cpa16(sbV + (uint32_t)(s * VLDW + cq) * 4, vp + go);
        }
        CP_COMMIT();
        CP_WAIT0();
        __syncthreads();

        float sacc[8][4];
        #pragma unroll
        for (int j = 0; j < 8; ++j)
            #pragma unroll
            for (int c = 0; c < 4; ++c) sacc[j][c] = 0.f;

        #pragma unroll
        for (int kc = 0; kc < 8; ++kc) {
            const int koff = kc * 8 + 2 * tig;
            float2 a02 = *(const float2*)&Qs[(wm + grp    ) * ALDW + koff];
            float2 a13 = *(const float2*)&Qs[(wm + grp + 8) * ALDW + koff];
            #pragma unroll
            for (int j = 0; j < 8; ++j) {
                float2 b01 = *(const float2*)&Ks[(j * 8 + grp) * ALDW + koff];
                mma_tf32(sacc[j],
                    __float_as_uint(a02.x), __float_as_uint(a13.x),
                    __float_as_uint(a02.y), __float_as_uint(a13.y),
                    __float_as_uint(b01.x), __float_as_uint(b01.y));
            }
        }

        if (kt >= 2 * qb) {
            #pragma unroll
            for (int j = 0; j < 8; ++j)
                #pragma unroll
                for (int c = 0; c < 4; ++c) {
                    const int row = qb * 128 + wm + grp + (c >> 1) * 8;
                    const int col = kt * 64 + j * 8 + 2 * tig + (c & 1);
                    if (col > row) sacc[j][c] = -1e30f;
                }
        }

        float alpha[2];
        #pragma unroll
        for (int rh = 0; rh < 2; ++rh) {
            float rm = -1e30f;
            #pragma unroll
            for (int j = 0; j < 8; ++j)
                rm = fmaxf(rm, fmaxf(sacc[j][rh*2], sacc[j][rh*2+1]));
            rm = fmaxf(rm, __shfl_xor_sync(0xffffffffu, rm, 1));
            rm = fmaxf(rm, __shfl_xor_sync(0xffffffffu, rm, 2));
            const float mn = fmaxf(m[rh], rm);
            alpha[rh] = __expf(m[rh] - mn);
            m[rh] = mn;
            float rs = 0.f;
            #pragma unroll
            for (int j = 0; j < 8; ++j) {
                float p0 = __expf(sacc[j][rh*2  ] - mn);
                float p1 = __expf(sacc[j][rh*2+1] - mn);
                sacc[j][rh*2] = p0; sacc[j][rh*2+1] = p1;
                rs += p0 + p1;
            }
            rs += __shfl_xor_sync(0xffffffffu, rs, 1);
            rs += __shfl_xor_sync(0xffffffffu, rs, 2);
            l[rh] = l[rh] * alpha[rh] + rs;
            #pragma unroll
            for (int j = 0; j < 8; ++j) {
                o[j][rh*2]   *= alpha[rh];
                o[j][rh*2+1] *= alpha[rh];
            }
        }

        __syncthreads();
        #pragma unroll
        for (int j = 0; j < 8; ++j) {
            #pragma unroll
            for (int rh = 0; rh < 2; ++rh) {
                const int row = wm + grp + rh * 8;
                float2 p2 = make_float2(
                    __uint_as_float(f2tf32(sacc[j][rh*2])),
                    __uint_as_float(f2tf32(sacc[j][rh*2+1])));
                *(float2*)&Ps[row * ALDW + j * 8 + 2 * tig] = p2;
            }
        }
        __syncthreads();

        #pragma unroll
        for (int ss = 0; ss < 8; ++ss) {
            const int koff = ss * 8 + 2 * tig;
            float2 a02 = *(const float2*)&Ps[(wm + grp    ) * ALDW + koff];
            float2 a13 = *(const float2*)&Ps[(wm + grp + 8) * ALDW + koff];
            #pragma unroll
            for (int j = 0; j < 8; ++j) {
                const int col = j * 8 + grp;
                const float b0 = Vs[koff * VLDW + col];
                const float b1 = Vs[(koff + 1) * VLDW + col];
                mma_tf32(o[j],
                    __float_as_uint(a02.x), __float_as_uint(a13.x),
                    __float_as_uint(a02.y), __float_as_uint(a13.y),
                    __float_as_uint(b0),    __float_as_uint(b1));
            }
        }
        __syncthreads();
    }

    const float inv0 = 1.0f / l[0];
    const float inv1 = 1.0f / l[1];
    #pragma unroll
    for (int j = 0; j < 8; ++j) {
        const int col = h * HSZ + j * 8 + 2 * tig;
        #pragma unroll
        for (int rh = 0; rh < 2; ++rh) {
            const float inv = rh ? inv1 : inv0;
            const int row = qb * 128 + wm + grp + rh * 8;
            float2 v2 = make_float2(
                __uint_as_float(f2tf32(o[j][rh*2]   * inv)),
                __uint_as_float(f2tf32(o[j][rh*2+1] * inv)));
            *(float2*)&g_att[((size_t)b * TT + row) * EE + col] = v2;
        }
    }
}

// ---------------------------------------------------------------------------
extern "C" void kernel_launch(void* const* d_in, const int* in_sizes, int n_in,
                              void* d_out, int out_size)
{
    const float* x  = (const float*)d_in[0];
    const float* Wk = (const float*)d_in[1];
    const float* Wq = (const float*)d_in[2];
    const float* Wv = (const float*)d_in[3];
    const float* Wp = (const float*)d_in[4];
    float* out = (float*)d_out;

    cudaFuncSetAttribute(qkv_gemm_kernel,
                         cudaFuncAttributeMaxDynamicSharedMemorySize, GSMEM);
    cudaFuncSetAttribute(proj_gemm_kernel,
                         cudaFuncAttributeMaxDynamicSharedMemorySize, GSMEM);
    cudaFuncSetAttribute(attn_mma_kernel,
                         cudaFuncAttributeMaxDynamicSharedMemorySize, ASMEM);

    const size_t total4 = (XN + 4 * WN) / 4;
    round_tf32_kernel<<<(unsigned)((total4 + 255) / 256), 256>>>(x, Wq, Wk, Wv, Wp);

    qkv_gemm_kernel<<<dim3(EE / 128, MTOT / 128, 3), 256, GSMEM>>>();

    attn_mma_kernel<<<dim3(TT / 128, HH, BB), 256, ASMEM>>>();

    proj_gemm_kernel<<<dim3(EE / 128, MTOT / 128), 256, GSMEM>>>(out);
}

// round 15
// speedup vs baseline: 1.0451x; 1.0451x over previous
// R14: GEMM reverted to R6 skeleton (BK=32, 2-stage — best known), plus
// register-double-buffered b-fragments (one ks ahead) to cover LDS->HMMA
// latency. Attention/prepass/epilogues identical to R6 (bit-identical math).
#include <cuda_runtime.h>
#include <stdint.h>

#define BB  8
#define TT  1024
#define EE  1024
#define HH  16
#define HSZ 64
#define MTOT (BB*TT)
#define XN  ((size_t)MTOT*EE)
#define WN  ((size_t)EE*EE)

__device__ __align__(16) float g_q[(size_t)BB*HH*TT*HSZ];   // tf32, pre-scaled
__device__ __align__(16) float g_k[(size_t)BB*HH*TT*HSZ];   // tf32
__device__ __align__(16) float g_v[(size_t)BB*HH*TT*HSZ];   // tf32
__device__ __align__(16) float g_att[XN];
__device__ __align__(16) float g_xt[XN];
__device__ __align__(16) float g_wt[4*WN];

__device__ __forceinline__ unsigned f2tf32(float f) {
    unsigned r; asm("cvt.rna.tf32.f32 %0, %1;" : "=r"(r) : "f"(f));
    return r;
}
__device__ __forceinline__ void mma_tf32(float c[4],
    unsigned a0, unsigned a1, unsigned a2, unsigned a3,
    unsigned b0, unsigned b1)
{
    asm volatile(
        "mma.sync.aligned.m16n8k8.row.col.f32.tf32.tf32.f32 "
        "{%0,%1,%2,%3}, {%4,%5,%6,%7}, {%8,%9}, {%0,%1,%2,%3};"
        : "+f"(c[0]), "+f"(c[1]), "+f"(c[2]), "+f"(c[3])
        : "r"(a0), "r"(a1), "r"(a2), "r"(a3), "r"(b0), "r"(b1));
}
__device__ __forceinline__ uint32_t s2u(const void* p) {
    uint32_t a;
    asm("{ .reg .u64 t; cvta.to.shared.u64 t, %1; cvt.u32.u64 %0, t; }"
        : "=r"(a) : "l"(p));
    return a;
}
__device__ __forceinline__ void cpa16(uint32_t dst, const void* src) {
    asm volatile("cp.async.cg.shared.global [%0], [%1], 16;"
                 :: "r"(dst), "l"(src) : "memory");
}
#define CP_COMMIT() asm volatile("cp.async.commit_group;" ::: "memory")
#define CP_WAIT1()  asm volatile("cp.async.wait_group 1;" ::: "memory")
#define CP_WAIT0()  asm volatile("cp.async.wait_group 0;" ::: "memory")

// ---------------------------------------------------------------------------
// prepass: round x and the 4 weight matrices to tf32 precision
// ---------------------------------------------------------------------------
__global__ __launch_bounds__(256) void round_tf32_kernel(
    const float* __restrict__ x,  const float* __restrict__ wq,
    const float* __restrict__ wk, const float* __restrict__ wv,
    const float* __restrict__ wp)
{
    const size_t i4 = (size_t)blockIdx.x * blockDim.x + threadIdx.x;
    const size_t e  = i4 * 4;
    if (e >= XN + 4 * WN) return;

    const float* src; float* dst; size_t off;
    if (e < XN) { src = x; dst = g_xt; off = e; }
    else {
        const size_t we = e - XN;
        const int z = (int)(we / WN);
        off = we - (size_t)z * WN;
        src = (z == 0) ? wq : (z == 1) ? wk : (z == 2) ? wv : wp;
        dst = g_wt + (size_t)z * WN;
    }
    float4 v = *(const float4*)(src + off);
    v.x = __uint_as_float(f2tf32(v.x));
    v.y = __uint_as_float(f2tf32(v.y));
    v.z = __uint_as_float(f2tf32(v.z));
    v.w = __uint_as_float(f2tf32(v.w));
    *(float4*)(dst + off) = v;
}

// ---------------------------------------------------------------------------
// TF32 GEMM: C = A @ W^T. 128x128 tile, BK=32, 8 warps (4m x 2n),
// 2-stage cp.async (R6 skeleton). b-fragments register-double-buffered one
// ks ahead so each ks's 16 mma overlap the next ks's 8 LDS.64.
// ---------------------------------------------------------------------------
#define LDW   40
#define TILEF (128*LDW)              // 5120 floats
#define GSMEM (2*2*TILEF*4)          // 81920 B

__device__ __forceinline__ void gemm_stage(
    uint32_t sbuf, const float* __restrict__ A, const float* __restrict__ W,
    int c)
{
    const int tid = threadIdx.x;
    // 2048 16B-chunks: [matrix(2)][row(128)][chunk(8)]
    #pragma unroll
    for (int u = 0; u < 8; ++u) {
        const int i   = tid + u * 256;
        const int mat = i >> 10;
        const int j   = i & 1023;
        const int row = j >> 3;
        const int cq  = (j & 7) * 4;
        const float* src = (mat ? W : A) + (size_t)row * EE + c * 32 + cq;
        const uint32_t dst = sbuf + (uint32_t)(mat * TILEF + row * LDW + cq) * 4;
        cpa16(dst, src);
    }
}

__device__ __forceinline__ void gemm_core(
    const float* __restrict__ A, const float* __restrict__ W,
    float acc[2][8][4], float* sm)
{
    const int tid  = threadIdx.x;
    const int wid  = tid >> 5;
    const int lane = tid & 31;
    const int grp  = lane >> 2;
    const int tig  = lane & 3;
    const int warpM = (wid & 3) * 32;
    const int warpN = (wid >> 2) * 64;
    const uint32_t sb = s2u(sm);

    gemm_stage(sb, A, W, 0); CP_COMMIT();
    gemm_stage(sb + 2 * TILEF * 4, A, W, 1); CP_COMMIT();

    const int NKT = EE / 32;   // 32
    const int aoff = (warpM + grp) * LDW + 2 * tig;
    const int boff = (warpN + grp) * LDW + 2 * tig;

    #pragma unroll 1
    for (int c = 0; c < NKT; ++c) {
        CP_WAIT1();
        __syncthreads();
        const float* as = sm + (c & 1) * 2 * TILEF;
        const float* aF = as + aoff;
        const float* bF = as + TILEF + boff;

        // preload b-fragments for ks=0
        float2 bfr[2][8];
        #pragma unroll
        for (int j = 0; j < 8; ++j)
            bfr[0][j] = *(const float2*)(bF + j * 8 * LDW);

        #pragma unroll
        for (int ks = 0; ks < 4; ++ks) {
            const int ko  = ks * 8;
            const int cur = ks & 1;
            // a-fragments for this ks (4 independent LDS.64)
            float2 a02_0 = *(const float2*)(aF + ko);
            float2 a13_0 = *(const float2*)(aF + 8 * LDW + ko);
            float2 a02_1 = *(const float2*)(aF + 16 * LDW + ko);
            float2 a13_1 = *(const float2*)(aF + 24 * LDW + ko);
            // preload b for next ks (8 independent LDS.64; covers a-latency too)
            if (ks < 3) {
                #pragma unroll
                for (int j = 0; j < 8; ++j)
                    bfr[cur ^ 1][j] = *(const float2*)(bF + j * 8 * LDW + ko + 8);
            }
            // 16 mma on current fragments
            #pragma unroll
            for (int j = 0; j < 8; ++j) {
                const float2 b01 = bfr[cur][j];
                mma_tf32(acc[0][j],
                    __float_as_uint(a02_0.x), __float_as_uint(a13_0.x),
                    __float_as_uint(a02_0.y), __float_as_uint(a13_0.y),
                    __float_as_uint(b01.x),   __float_as_uint(b01.y));
                mma_tf32(acc[1][j],
                    __float_as_uint(a02_1.x), __float_as_uint(a13_1.x),
                    __float_as_uint(a02_1.y), __float_as_uint(a13_1.y),
                    __float_as_uint(b01.x),   __float_as_uint(b01.y));
            }
        }
        __syncthreads();
        if (c + 2 < NKT)
            gemm_stage(sb + (c & 1) * 2 * TILEF * 4, A, W, c + 2);
        CP_COMMIT();
    }
}

// QKV: epilogue writes tf32-rounded q/k/v, q pre-scaled by HS^-0.5 = 0.125.
__global__ __launch_bounds__(256, 2) void qkv_gemm_kernel()
{
    extern __shared__ __align__(16) float sm[];
    const int z = blockIdx.z;
    const int blockM = blockIdx.y * 128, blockN = blockIdx.x * 128;

    float acc[2][8][4];
    #pragma unroll
    for (int i = 0; i < 2; ++i)
        #pragma unroll
        for (int j = 0; j < 8; ++j)
            #pragma unroll
            for (int c = 0; c < 4; ++c) acc[i][j][c] = 0.f;

    gemm_core(g_xt + (size_t)blockM * EE,
              g_wt + (size_t)z * WN + (size_t)blockN * EE, acc, sm);

    float* dst = (z == 0) ? g_q : (z == 1) ? g_k : g_v;
    const float scl = (z == 0) ? 0.125f : 1.0f;
    const int wid = threadIdx.x >> 5, lane = threadIdx.x & 31;
    const int grp = lane >> 2, tig = lane & 3;
    const int warpM = (wid & 3) * 32, warpN = (wid >> 2) * 64;

    #pragma unroll
    for (int i = 0; i < 2; ++i) {
        #pragma unroll
        for (int j = 0; j < 8; ++j) {
            const int col = blockN + warpN + j*8 + tig*2;
            const int h = col >> 6, d = col & 63;
            #pragma unroll
            for (int rh = 0; rh < 2; ++rh) {
                const int row = blockM + warpM + i*16 + grp + rh*8;
                const int b = row >> 10, t = row & (TT-1);
                float2 v2 = make_float2(
                    __uint_as_float(f2tf32(acc[i][j][rh*2]   * scl)),
                    __uint_as_float(f2tf32(acc[i][j][rh*2+1] * scl)));
                *(float2*)&dst[((size_t)(b*HH + h)*TT + t)*HSZ + d] = v2;
            }
        }
    }
}

__global__ __launch_bounds__(256, 2) void proj_gemm_kernel(float* __restrict__ out)
{
    extern __shared__ __align__(16) float sm[];
    const int blockM = blockIdx.y * 128, blockN = blockIdx.x * 128;

    float acc[2][8][4];
    #pragma unroll
    for (int i = 0; i < 2; ++i)
        #pragma unroll
        for (int j = 0; j < 8; ++j)
            #pragma unroll
            for (int c = 0; c < 4; ++c) acc[i][j][c] = 0.f;

    gemm_core(g_att + (size_t)blockM * EE,
              g_wt + 3 * WN + (size_t)blockN * EE, acc, sm);

    const int wid = threadIdx.x >> 5, lane = threadIdx.x & 31;
    const int grp = lane >> 2, tig = lane & 3;
    const int warpM = (wid & 3) * 32, warpN = (wid >> 2) * 64;

    #pragma unroll
    for (int i = 0; i < 2; ++i) {
        #pragma unroll
        for (int j = 0; j < 8; ++j) {
            const int col = blockN + warpN + j*8 + tig*2;
            #pragma unroll
            for (int rh = 0; rh < 2; ++rh) {
                const int row = blockM + warpM + i*16 + grp + rh*8;
                float2 v2 = make_float2(acc[i][j][rh*2], acc[i][j][rh*2+1]);
                *(float2*)&out[(size_t)row*EE + col] = v2;
            }
        }
    }
}

// ---------------------------------------------------------------------------
// Causal flash attention, mma.sync tf32 (unchanged from R6/R8).
// ---------------------------------------------------------------------------
#define ALDW 72
#define VLDW 68
#define ASMEM ((128*ALDW + 64*ALDW + 64*VLDW + 128*ALDW) * 4)

__global__ __launch_bounds__(256, 2) void attn_mma_kernel()
{
    extern __shared__ __align__(16) float sm[];
    float* Qs = sm;
    float* Ks = Qs + 128 * ALDW;
    float* Vs = Ks + 64 * ALDW;
    float* Ps = Vs + 64 * VLDW;

    const int qb = blockIdx.x, h = blockIdx.y, b = blockIdx.z;
    const float* qp = g_q + ((size_t)(b * HH + h) * TT + qb * 128) * HSZ;
    const float* kp = g_k + ((size_t)(b * HH + h) * TT) * HSZ;
    const float* vp = g_v + ((size_t)(b * HH + h) * TT) * HSZ;

    const int tid  = threadIdx.x;
    const int wid  = tid >> 5;
    const int lane = tid & 31;
    const int grp  = lane >> 2;
    const int tig  = lane & 3;
    const int wm   = wid * 16;
    const uint32_t sb = s2u(sm);
    const uint32_t sbK = sb + 128 * ALDW * 4;
    const uint32_t sbV = sbK + 64 * ALDW * 4;

    #pragma unroll
    for (int u = 0; u < 8; ++u) {
        const int i = tid + u * 256;
        const int row = i >> 4, cq = (i & 15) * 4;
        cpa16(sb + (uint32_t)(row * ALDW + cq) * 4,
              qp + (size_t)row * HSZ + cq);
    }

    float m[2], l[2], o[8][4];
    m[0] = m[1] = -1e30f; l[0] = l[1] = 0.f;
    #pragma unroll
    for (int j = 0; j < 8; ++j)
        #pragma unroll
        for (int c = 0; c < 4; ++c) o[j][c] = 0.f;

    const int ntiles = 2 * qb + 2;

    for (int kt = 0; kt < ntiles; ++kt) {
        #pragma unroll
        for (int u = 0; u < 4; ++u) {
            const int i = tid + u * 256;
            const int s = i >> 4, cq = (i & 15) * 4;
            const size_t go = (size_t)(kt * 64 + s) * HSZ + cq;
            cpa16(sbK + (uint32_t)(s * ALDW + cq) * 4, kp + go);
            cpa16(sbV + (uint32_t)(s * VLDW + cq) * 4, vp + go);
        }
        CP_COMMIT();
        CP_WAIT0();
        __syncthreads();

        float sacc[8][4];
        #pragma unroll
        for (int j = 0; j < 8; ++j)
            #pragma unroll
            for (int c = 0; c < 4; ++c) sacc[j][c] = 0.f;

        #pragma unroll
        for (int kc = 0; kc < 8; ++kc) {
            const int koff = kc * 8 + 2 * tig;
            float2 a02 = *(const float2*)&Qs[(wm + grp    ) * ALDW + koff];
            float2 a13 = *(const float2*)&Qs[(wm + grp + 8) * ALDW + koff];
            #pragma unroll
            for (int j = 0; j < 8; ++j) {
                float2 b01 = *(const float2*)&Ks[(j * 8 + grp) * ALDW + koff];
                mma_tf32(sacc[j],
                    __float_as_uint(a02.x), __float_as_uint(a13.x),
                    __float_as_uint(a02.y), __float_as_uint(a13.y),
                    __float_as_uint(b01.x), __float_as_uint(b01.y));
            }
        }

        if (kt >= 2 * qb) {
            #pragma unroll
            for (int j = 0; j < 8; ++j)
                #pragma unroll
                for (int c = 0; c < 4; ++c) {
                    const int row = qb * 128 + wm + grp + (c >> 1) * 8;
                    const int col = kt * 64 + j * 8 + 2 * tig + (c & 1);
                    if (col > row) sacc[j][c] = -1e30f;
                }
        }

        float alpha[2];
        #pragma unroll
        for (int rh = 0; rh < 2; ++rh) {
            float rm = -1e30f;
            #pragma unroll
            for (int j = 0; j < 8; ++j)
                rm = fmaxf(rm, fmaxf(sacc[j][rh*2], sacc[j][rh*2+1]));
            rm = fmaxf(rm, __shfl_xor_sync(0xffffffffu, rm, 1));
            rm = fmaxf(rm, __shfl_xor_sync(0xffffffffu, rm, 2));
            const float mn = fmaxf(m[rh], rm);
            alpha[rh] = __expf(m[rh] - mn);
            m[rh] = mn;
            float rs = 0.f;
            #pragma unroll
            for (int j = 0; j < 8; ++j) {
                float p0 = __expf(sacc[j][rh*2  ] - mn);
                float p1 = __expf(sacc[j][rh*2+1] - mn);
                sacc[j][rh*2] = p0; sacc[j][rh*2+1] = p1;
                rs += p0 + p1;
            }
            rs += __shfl_xor_sync(0xffffffffu, rs, 1);
            rs += __shfl_xor_sync(0xffffffffu, rs, 2);
            l[rh] = l[rh] * alpha[rh] + rs;
            #pragma unroll
            for (int j = 0; j < 8; ++j) {
                o[j][rh*2]   *= alpha[rh];
                o[j][rh*2+1] *= alpha[rh];
            }
        }

        __syncthreads();
        #pragma unroll
        for (int j = 0; j < 8; ++j) {
            #pragma unroll
            for (int rh = 0; rh < 2; ++rh) {
                const int row = wm + grp + rh * 8;
                float2 p2 = make_float2(
                    __uint_as_float(f2tf32(sacc[j][rh*2])),
                    __uint_as_float(f2tf32(sacc[j][rh*2+1])));
                *(float2*)&Ps[row * ALDW + j * 8 + 2 * tig] = p2;
            }
        }
        __syncthreads();

        #pragma unroll
        for (int ss = 0; ss < 8; ++ss) {
            const int koff = ss * 8 + 2 * tig;
            float2 a02 = *(const float2*)&Ps[(wm + grp    ) * ALDW + koff];
            float2 a13 = *(const float2*)&Ps[(wm + grp + 8) * ALDW + koff];
            #pragma unroll
            for (int j = 0; j < 8; ++j) {
                const int col = j * 8 + grp;
                const float b0 = Vs[koff * VLDW + col];
                const float b1 = Vs[(koff + 1) * VLDW + col];
                mma_tf32(o[j],
                    __float_as_uint(a02.x), __float_as_uint(a13.x),
                    __float_as_uint(a02.y), __float_as_uint(a13.y),
                    __float_as_uint(b0),    __float_as_uint(b1));
            }
        }
        __syncthreads();
    }

    const float inv0 = 1.0f / l[0];
    const float inv1 = 1.0f / l[1];
    #pragma unroll
    for (int j = 0; j < 8; ++j) {
        const int col = h * HSZ + j * 8 + 2 * tig;
        #pragma unroll
        for (int rh = 0; rh < 2; ++rh) {
            const float inv = rh ? inv1 : inv0;
            const int row = qb * 128 + wm + grp + rh * 8;
            float2 v2 = make_float2(
                __uint_as_float(f2tf32(o[j][rh*2]   * inv)),
                __uint_as_float(f2tf32(o[j][rh*2+1] * inv)));
            *(float2*)&g_att[((size_t)b * TT + row) * EE + col] = v2;
        }
    }
}

// ---------------------------------------------------------------------------
extern "C" void kernel_launch(void* const* d_in, const int* in_sizes, int n_in,
                              void* d_out, int out_size)
{
    const float* x  = (const float*)d_in[0];
    const float* Wk = (const float*)d_in[1];
    const float* Wq = (const float*)d_in[2];
    const float* Wv = (const float*)d_in[3];
    const float* Wp = (const float*)d_in[4];
    float* out = (float*)d_out;

    cudaFuncSetAttribute(qkv_gemm_kernel,
                         cudaFuncAttributeMaxDynamicSharedMemorySize, GSMEM);
    cudaFuncSetAttribute(proj_gemm_kernel,
                         cudaFuncAttributeMaxDynamicSharedMemorySize, GSMEM);
    cudaFuncSetAttribute(attn_mma_kernel,
                         cudaFuncAttributeMaxDynamicSharedMemorySize, ASMEM);

    const size_t total4 = (XN + 4 * WN) / 4;
    round_tf32_kernel<<<(unsigned)((total4 + 255) / 256), 256>>>(x, Wq, Wk, Wv, Wp);

    qkv_gemm_kernel<<<dim3(EE / 128, MTOT / 128, 3), 256, GSMEM>>>();

    attn_mma_kernel<<<dim3(TT / 128, HH, BB), 256, ASMEM>>>();

    proj_gemm_kernel<<<dim3(EE / 128, MTOT / 128), 256, GSMEM>>>(out);
}